// round 8
// baseline (speedup 1.0000x reference)
#include <cuda_runtime.h>
#include <cstdint>

// 2-layer LSTM, H=6, F=6, B=4096, T=1024.
// 2 batch elements per warp (16-lane segments), 12 active lanes per element:
// lane (l,k) owns hidden index k of layer l and computes all four gate rows
// (i,f,g,o) for it, SCALAR (no f32x2 packing -> no pack/unpack ALU ops).
// Cell recurrence strictly lane-local. State exchange = 12x 32-bit SHFL/step:
//   rec_q = shfl(h, 6l+q, 16)   (own layer's recurrent h)
//   tmp_q = shfl(h, q,    16)   (h0, layer1's input; layer0 selects x instead)
// 2048 warps (vs 1024 in R5-R7) -> 3.46 warps/SMSP for latency hiding.
// Software-pipelined: iteration t computes layer0(t+1) and layer1(t).
// Activations: tanh.approx; sigmoid = 0.5*tanh(z/2)+0.5, 0.5 folded into weights.

#define WARPS_PER_BLOCK 4
#define THREADS (WARPS_PER_BLOCK * 32)
#define ELEMS_PER_WARP 2
#define T_LEN 1024
#define TCHUNK 32
#define NCHUNK (T_LEN / TCHUNK)
#define CSTRIDE 200                 // padded per-element smem stride (floats)
#define CSTRIDE4 (CSTRIDE / 4)

__device__ __forceinline__ float tanha(float x) {
    float y; asm("tanh.approx.f32 %0, %1;" : "=f"(y) : "f"(x)); return y;
}

__global__ __launch_bounds__(THREADS, 1)
void lstm2_kernel(const float* __restrict__ x,
                  const float* __restrict__ wih0, const float* __restrict__ whh0,
                  const float* __restrict__ bih0, const float* __restrict__ bhh0,
                  const float* __restrict__ wih1, const float* __restrict__ whh1,
                  const float* __restrict__ bih1, const float* __restrict__ bhh1,
                  float* __restrict__ out)
{
    __shared__ float sx[2][WARPS_PER_BLOCK][ELEMS_PER_WARP * CSTRIDE];
    __shared__ float so[WARPS_PER_BLOCK][ELEMS_PER_WARP * CSTRIDE];

    const int lane = threadIdx.x & 31;
    const int warp = threadIdx.x >> 5;
    const int e    = lane >> 4;                         // element within warp
    const int s    = lane & 15;                         // lane within segment
    const int l    = (s >= 6 && s < 12) ? 1 : 0;        // layer owned
    const int k    = (s < 6) ? s : ((s < 12) ? s - 6 : 0);
    const int loff = l * 6;                             // shuffle base for rec
    const bool wr  = (s >= 6 && s < 12);                // layer1 lanes store h

    const int b0 = (blockIdx.x * WARPS_PER_BLOCK + warp) * ELEMS_PER_WARP;

    // ---- per-lane scalar weights: 4 gate rows of hidden k, layer l ----
    const float* wih = l ? wih1 : wih0;
    const float* whh = l ? whh1 : whh0;
    const float* bih = l ? bih1 : bih0;
    const float* bhh = l ? bhh1 : bhh0;

    float wx[4][6], wh[4][6], bs[4];
#pragma unroll
    for (int g = 0; g < 4; g++) {
        const float sc = (g == 2) ? 1.0f : 0.5f;   // sigmoid rows pre-scaled
        const int row = g * 6 + k;
#pragma unroll
        for (int q = 0; q < 6; q++) {
            wx[g][q] = wih[row * 6 + q] * sc;
            wh[g][q] = whh[row * 6 + q] * sc;
        }
        bs[g] = (bih[row] + bhh[row]) * sc;
    }

    float h = 0.0f, cc = 0.0f;

    auto stage = [&](int c, int buf) {
        float4* dst = reinterpret_cast<float4*>(sx[buf][warp]);
#pragma unroll
        for (int i = 0; i < 3; i++) {                  // 96 float4 per warp
            int idx = i * 32 + lane;
            int ee  = idx / 48;
            int off = idx - ee * 48;
            const float4* src = reinterpret_cast<const float4*>(
                x + (size_t)(b0 + ee) * (T_LEN * 6) + c * (TCHUNK * 6));
            dst[ee * CSTRIDE4 + off] = src[off];
        }
    };

    // one LSTM step for this lane; xr -> 6 input floats (layer0's input)
    auto body = [&](const float* xr) {
        float xv[6];
        {
            const float2* x2 = reinterpret_cast<const float2*>(xr);
            float2 a = x2[0], b2 = x2[1], c2 = x2[2];
            xv[0] = a.x;  xv[1] = a.y;
            xv[2] = b2.x; xv[3] = b2.y;
            xv[4] = c2.x; xv[5] = c2.y;
        }
        float rq[6], tq[6];
#pragma unroll
        for (int q = 0; q < 6; q++) {
            tq[q] = __shfl_sync(0xffffffffu, h, q, 16);         // h0_q
            rq[q] = __shfl_sync(0xffffffffu, h, loff + q, 16);  // own layer rec
        }

        // split chains: q 0..2 (bias-seeded) and q 3..5
        float zl[4], zh[4];
#pragma unroll
        for (int g = 0; g < 4; g++) { zl[g] = bs[g]; zh[g] = 0.0f; }
#pragma unroll
        for (int q = 0; q < 3; q++) {
            const float inp = l ? tq[q] : xv[q];
#pragma unroll
            for (int g = 0; g < 4; g++) {
                zl[g] = fmaf(wx[g][q], inp, zl[g]);
                zl[g] = fmaf(wh[g][q], rq[q], zl[g]);
            }
        }
#pragma unroll
        for (int q = 3; q < 6; q++) {
            const float inp = l ? tq[q] : xv[q];
#pragma unroll
            for (int g = 0; g < 4; g++) {
                zh[g] = fmaf(wx[g][q], inp, zh[g]);
                zh[g] = fmaf(wh[g][q], rq[q], zh[g]);
            }
        }

        const float gi = fmaf(0.5f, tanha(zl[0] + zh[0]), 0.5f);
        const float gf = fmaf(0.5f, tanha(zl[1] + zh[1]), 0.5f);
        const float gg = tanha(zl[2] + zh[2]);
        const float go = fmaf(0.5f, tanha(zl[3] + zh[3]), 0.5f);

        cc = fmaf(gf, cc, gi * gg);
        h  = go * tanha(cc);
    };

    // ---- prologue: stage chunk 0; run step with x(0); reset layer1 state ----
    stage(0, 0);
    __syncwarp();
    body(&sx[0][warp][e * CSTRIDE]);
    if (l) { h = 0.0f; cc = 0.0f; }   // layer1 hasn't run a real step yet

    // ---- main loop: iteration t computes layer0(t+1) and layer1(t) ----
    for (int c = 0; c < NCHUNK; c++) {
        if (c + 1 < NCHUNK) stage(c + 1, (c + 1) & 1);
        __syncwarp();

        const float* bcur = sx[c & 1][warp] + e * CSTRIDE;
        const float* bnxt = sx[(c + 1) & 1][warp] + e * CSTRIDE;

#pragma unroll 4
        for (int dt = 0; dt < TCHUNK; dt++) {
            const float* xr = (dt < TCHUNK - 1) ? (bcur + (dt + 1) * 6) : bnxt;
            body(xr);
            if (wr) so[warp][e * CSTRIDE + dt * 6 + k] = h;   // h1(t)
        }
        __syncwarp();

        // ---- flush output chunk (96 float4 per warp) ----
        {
            const float4* src = reinterpret_cast<const float4*>(so[warp]);
#pragma unroll
            for (int i = 0; i < 3; i++) {
                int idx = i * 32 + lane;
                int ee  = idx / 48;
                int off = idx - ee * 48;
                float4* dst = reinterpret_cast<float4*>(
                    out + (size_t)(b0 + ee) * (T_LEN * 6) + c * (TCHUNK * 6));
                dst[off] = src[ee * CSTRIDE4 + off];
            }
        }
        __syncwarp();
    }
}

extern "C" void kernel_launch(void* const* d_in, const int* in_sizes, int n_in,
                              void* d_out, int out_size)
{
    const float* x    = (const float*)d_in[0];
    const float* wih0 = (const float*)d_in[1];
    const float* whh0 = (const float*)d_in[2];
    const float* bih0 = (const float*)d_in[3];
    const float* bhh0 = (const float*)d_in[4];
    const float* wih1 = (const float*)d_in[5];
    const float* whh1 = (const float*)d_in[6];
    const float* bih1 = (const float*)d_in[7];
    const float* bhh1 = (const float*)d_in[8];
    float* out = (float*)d_out;

    const int B = in_sizes[0] / (T_LEN * 6);                   // 4096
    const int grid = B / (WARPS_PER_BLOCK * ELEMS_PER_WARP);   // 512

    lstm2_kernel<<<grid, THREADS>>>(x, wih0, whh0, bih0, bhh0,
                                    wih1, whh1, bih1, bhh1, out);
}

// round 9
// speedup vs baseline: 1.2399x; 1.2399x over previous
#include <cuda_runtime.h>
#include <cstdint>

// 2-layer LSTM, H=6, F=6, B=4096, T=1024.
// 2 elems/warp, 12 active lanes/elem: lane (l,k) owns hidden k of layer l,
// computes all 4 gate rows. K-dimension packed f32x2: operand pairs loaded
// directly as ld.shared.b64 -> zero pack MOVs. h-state exchanged through a
// double-buffered smem slot (1 STS + LDS.64s + 1 syncwarp; no shuffles).
// Balanced grid: 148 blocks x 14 warps = 1 block/SM exactly.
// Pipelined: main step m computes layer0(t=m) and layer1(t=m-1).
// Activations: tanh.approx; sigmoid = 0.5*tanh(z/2)+0.5 folded into weights.

#define WARPS_PER_BLOCK 14
#define THREADS (WARPS_PER_BLOCK * 32)
#define T_LEN 1024
#define TCHUNK 16
#define NCHUNK (T_LEN / TCHUNK)     // 64
#define CSTRIDE 104                 // floats per elem per chunk (96 data + 8 pad)
#define CSTRIDE4 (CSTRIDE / 4)      // 26

typedef unsigned long long ull;

__device__ __forceinline__ float tanha(float x) {
    float y; asm("tanh.approx.f32 %0, %1;" : "=f"(y) : "f"(x)); return y;
}
__device__ __forceinline__ ull pk2(float lo, float hi) {
    ull r; asm("mov.b64 %0, {%1, %2};" : "=l"(r) : "f"(lo), "f"(hi)); return r;
}
__device__ __forceinline__ void upk2(float& lo, float& hi, ull v) {
    asm("mov.b64 {%0, %1}, %2;" : "=f"(lo), "=f"(hi) : "l"(v));
}
__device__ __forceinline__ ull fma2(ull a, ull b, ull c) {
    ull d; asm("fma.rn.f32x2 %0, %1, %2, %3;" : "=l"(d) : "l"(a), "l"(b), "l"(c));
    return d;
}
__device__ __forceinline__ ull lds64(uint32_t addr) {
    ull v; asm volatile("ld.shared.b64 %0, [%1];" : "=l"(v) : "r"(addr));
    return v;
}
__device__ __forceinline__ void sts32(uint32_t addr, float v) {
    asm volatile("st.shared.f32 [%0], %1;" :: "r"(addr), "f"(v) : "memory");
}

__global__ __launch_bounds__(THREADS, 1)
void lstm2_kernel(const float* __restrict__ x,
                  const float* __restrict__ wih0, const float* __restrict__ whh0,
                  const float* __restrict__ bih0, const float* __restrict__ bhh0,
                  const float* __restrict__ wih1, const float* __restrict__ whh1,
                  const float* __restrict__ bih1, const float* __restrict__ bhh1,
                  float* __restrict__ out, int B)
{
    __shared__ float sx[2][WARPS_PER_BLOCK][2 * CSTRIDE];
    __shared__ float soB[WARPS_PER_BLOCK][2 * CSTRIDE];
    __shared__ float hx[WARPS_PER_BLOCK][96];   // per warp: e*48 + slot*20 + l*8 + k

    const int lane = threadIdx.x & 31;
    const int warp = threadIdx.x >> 5;
    const int e    = lane >> 4;
    const int s    = lane & 15;
    const int l    = (s >= 6 && s < 12) ? 1 : 0;
    const int k    = (s < 6) ? s : ((s < 12) ? s - 6 : 0);
    const bool wr  = (s >= 6 && s < 12);

    const int b0 = (blockIdx.x * WARPS_PER_BLOCK + warp) * 2;
    if (b0 >= B) return;

    // ---- K-packed per-lane weights (4 gate rows of hidden k, layer l) ----
    const float* wih = l ? wih1 : wih0;
    const float* whh = l ? whh1 : whh0;
    const float* bih = l ? bih1 : bih0;
    const float* bhh = l ? bhh1 : bhh0;

    ull wx[4][3], wh[4][3], bz[4];
#pragma unroll
    for (int g = 0; g < 4; g++) {
        const float sc = (g == 2) ? 1.0f : 0.5f;
        const int row = g * 6 + k;
#pragma unroll
        for (int p = 0; p < 3; p++) {
            wx[g][p] = pk2(wih[row * 6 + 2 * p] * sc, wih[row * 6 + 2 * p + 1] * sc);
            wh[g][p] = pk2(whh[row * 6 + 2 * p] * sc, whh[row * 6 + 2 * p + 1] * sc);
        }
        bz[g] = pk2((bih[row] + bhh[row]) * sc, 0.0f);
    }

    // ---- smem addresses ----
    const uint32_t hx_u  = (uint32_t)__cvta_generic_to_shared(&hx[warp][0]);
    const uint32_t hxe_u = hx_u + e * 192;                  // e*48 floats
    const uint32_t recO  = hxe_u + l * 32;                  // rec base, slot0
    const uint32_t recE  = recO + 80;                       // rec base, slot1
    const uint32_t stO   = hxe_u + ((s < 12) ? (l * 8 + k) * 4 : 56);  // write slot0
    const uint32_t stE   = stO + 80;                        // write slot1
    uint32_t sx_u[2];
    sx_u[0] = (uint32_t)__cvta_generic_to_shared(&sx[0][warp][0]);
    sx_u[1] = (uint32_t)__cvta_generic_to_shared(&sx[1][warp][0]);

    // zero the h-exchange region (3 floats/lane covers 96)
    hx[warp][lane] = 0.0f; hx[warp][lane + 32] = 0.0f; hx[warp][lane + 64] = 0.0f;
    __syncwarp();

    float cc = 0.0f;

    auto stage = [&](int c, int buf) {
        float4* dst = reinterpret_cast<float4*>(sx[buf][warp]);
#pragma unroll
        for (int i = 0; i < 2; i++) {
            int idx = i * 32 + lane;              // 48 float4 total
            if (idx < 48) {
                int ee  = idx / 24;
                int off = idx - ee * 24;
                const float4* src = reinterpret_cast<const float4*>(
                    x + (size_t)(b0 + ee) * (T_LEN * 6) + c * (TCHUNK * 6));
                dst[ee * CSTRIDE4 + off] = src[off];
            }
        }
    };

    // one step: inp addr ia, rec addr ra, write addr wa; stores h1 if dt>=0
    auto step = [&](uint32_t ia, uint32_t ra, uint32_t wa, int dt) {
        const ull v0 = lds64(ia), v1 = lds64(ia + 8), v2 = lds64(ia + 16);
        const ull r0 = lds64(ra), r1 = lds64(ra + 8), r2 = lds64(ra + 16);

        ull z0 = fma2(wx[0][0], v0, bz[0]);
        ull z1 = fma2(wx[1][0], v0, bz[1]);
        ull z2 = fma2(wx[2][0], v0, bz[2]);
        ull z3 = fma2(wx[3][0], v0, bz[3]);
        z0 = fma2(wx[0][1], v1, z0); z1 = fma2(wx[1][1], v1, z1);
        z2 = fma2(wx[2][1], v1, z2); z3 = fma2(wx[3][1], v1, z3);
        z0 = fma2(wx[0][2], v2, z0); z1 = fma2(wx[1][2], v2, z1);
        z2 = fma2(wx[2][2], v2, z2); z3 = fma2(wx[3][2], v2, z3);
        z0 = fma2(wh[0][0], r0, z0); z1 = fma2(wh[1][0], r0, z1);
        z2 = fma2(wh[2][0], r0, z2); z3 = fma2(wh[3][0], r0, z3);
        z0 = fma2(wh[0][1], r1, z0); z1 = fma2(wh[1][1], r1, z1);
        z2 = fma2(wh[2][1], r1, z2); z3 = fma2(wh[3][1], r1, z3);
        z0 = fma2(wh[0][2], r2, z0); z1 = fma2(wh[1][2], r2, z1);
        z2 = fma2(wh[2][2], r2, z2); z3 = fma2(wh[3][2], r2, z3);

        float a, b2;
        upk2(a, b2, z0); const float zi = a + b2;
        upk2(a, b2, z1); const float zf = a + b2;
        upk2(a, b2, z2); const float zg = a + b2;
        upk2(a, b2, z3); const float zo = a + b2;

        const float gi = fmaf(0.5f, tanha(zi), 0.5f);
        const float gf = fmaf(0.5f, tanha(zf), 0.5f);
        const float gg = tanha(zg);
        const float go = fmaf(0.5f, tanha(zo), 0.5f);

        cc = fmaf(gf, cc, gi * gg);
        const float hn = go * tanha(cc);

        sts32(wa, hn);
        if (dt >= 0 && wr) soB[warp][e * CSTRIDE + dt * 6 + k] = hn;
        __syncwarp();
    };

    // ---- prologue (step 0): read slot0 (zeros), write slot1 ----
    stage(0, 0);
    __syncwarp();
    {
        const uint32_t ia = l ? (hxe_u + 0) : (sx_u[0] + e * 416 + 0);  // x(0) / h0-slot0
        step(ia, recO, stE, -1);
        // layer1 hasn't run a real step: reset its state
        const float hv = l ? 0.0f : 0.0f;   // overwrite only needed for l=1; rewrite is safe
        if (l) { cc = 0.0f; sts32(stE, 0.0f); }
        (void)hv;
        __syncwarp();
    }

    // ---- main loop: chunk c covers main steps m = c*16+1 .. c*16+16 ----
    for (int c = 0; c < NCHUNK; c++) {
        if (c + 1 < NCHUNK) stage(c + 1, (c + 1) & 1);
        __syncwarp();

        const uint32_t xb = sx_u[c & 1] + e * 416;
        const uint32_t xn = sx_u[(c + 1) & 1] + e * 416;
        uint32_t inpE = l ? (hxe_u + 80) : (xb + 24);   // even dt: read slot1
        uint32_t inpO = l ? (hxe_u +  0) : (xb + 48);   // odd dt: read slot0
        const uint32_t inpLast = l ? (hxe_u + 0) : xn;  // dt=15 reads next chunk
        const uint32_t sI = l ? 0u : 48u;

#pragma unroll
        for (int dt = 0; dt < TCHUNK; dt += 2) {
            // even dt: read slot1, write slot0
            step(inpE, recE, stO, dt);
            // odd dt: read slot0, write slot1
            const uint32_t ia = (dt + 1 == TCHUNK - 1) ? inpLast : inpO;
            step(ia, recO, stE, dt + 1);
            inpE += sI; inpO += sI;
        }

        // ---- flush h1 outputs for t in [c*16, c*16+16) ----
        {
            const float4* src = reinterpret_cast<const float4*>(soB[warp]);
#pragma unroll
            for (int i = 0; i < 2; i++) {
                int idx = i * 32 + lane;
                if (idx < 48) {
                    int ee  = idx / 24;
                    int off = idx - ee * 24;
                    float4* dst = reinterpret_cast<float4*>(
                        out + (size_t)(b0 + ee) * (T_LEN * 6) + c * (TCHUNK * 6));
                    dst[off] = src[ee * CSTRIDE4 + off];
                }
            }
        }
        __syncwarp();
    }
}

extern "C" void kernel_launch(void* const* d_in, const int* in_sizes, int n_in,
                              void* d_out, int out_size)
{
    const float* x    = (const float*)d_in[0];
    const float* wih0 = (const float*)d_in[1];
    const float* whh0 = (const float*)d_in[2];
    const float* bih0 = (const float*)d_in[3];
    const float* bhh0 = (const float*)d_in[4];
    const float* wih1 = (const float*)d_in[5];
    const float* whh1 = (const float*)d_in[6];
    const float* bih1 = (const float*)d_in[7];
    const float* bhh1 = (const float*)d_in[8];
    float* out = (float*)d_out;

    const int B = in_sizes[0] / (T_LEN * 6);                       // 4096
    const int grid = (B + 2 * WARPS_PER_BLOCK - 1) / (2 * WARPS_PER_BLOCK);  // 147 -> 148

    lstm2_kernel<<<grid, THREADS>>>(x, wih0, whh0, bih0, bhh0,
                                    wih1, whh1, bih1, bhh1, out, B);
}